// round 9
// baseline (speedup 1.0000x reference)
#include <cuda_runtime.h>
#include <cuda_bf16.h>
#include <math.h>
#include <stdint.h>

#define NN 10000
#define EE 160000
#define HH 256

// ---------------------------------------------------------------------------
// Scratch (no runtime allocation allowed)
// ---------------------------------------------------------------------------
__device__ float g_xcat[NN * 48];
__device__ float g_h[NN * HH];
__device__ float g_p[NN * HH];
__device__ float g_q[NN * HH];
__device__ float g_agg[NN * HH];
__device__ float g_t[NN * HH];
__device__ float g_u[NN * HH];
__device__ float g_wpa[256 * 256];
__device__ float g_wqb[256 * 256];
__device__ float g_wr2[32 * 256];
__device__ float g_cz[256];
// Transposed weights W^T[N=256, Kc=32] tiles, hi 8192 + lo 8192 bf16 each.
// tiles 0..7 = W2, 8..15 = W3, 16..23 = W4, 24 = Wr2 (K=32)
__device__ __align__(16) __nv_bfloat16 g_wt[25 * 16384];

__device__ __forceinline__ float gelu_f(float x) {
    float x3 = x * x * x;
    return 0.5f * x * (1.0f + tanhf(0.7978845608028654f * (x + 0.044715f * x3)));
}
__device__ __forceinline__ float lrelu_f(float x) { return x > 0.0f ? x : 0.01f * x; }

// ---------------------------------------------------------------------------
// PTX helpers (sm_80/sm_90 base ISA: valid at .target sm_100)
// ---------------------------------------------------------------------------
__device__ __forceinline__ uint32_t smem_u32(const void* p) {
    uint32_t a;
    asm("{ .reg .u64 t; cvta.to.shared.u64 t, %1; cvt.u32.u64 %0, t; }" : "=r"(a) : "l"(p));
    return a;
}
__device__ __forceinline__ void cp_async16(uint32_t smem_addr, const void* gptr) {
    asm volatile("cp.async.cg.shared.global [%0], [%1], 16;\n" :: "r"(smem_addr), "l"(gptr));
}
#define CP_COMMIT() asm volatile("cp.async.commit_group;\n" ::: "memory")
#define CP_WAIT0()  asm volatile("cp.async.wait_group 0;\n" ::: "memory")
#define CP_WAIT1()  asm volatile("cp.async.wait_group 1;\n" ::: "memory")

// SMEM -> GMEM bulk reduction (sm_90 base ISA)
__device__ __forceinline__ void bulk_reduce_add_f32(void* gdst, uint32_t ssrc, uint32_t bytes) {
    asm volatile("cp.reduce.async.bulk.global.shared::cta.bulk_group.add.f32 [%0], [%1], %2;\n"
                 :: "l"(gdst), "r"(ssrc), "r"(bytes) : "memory");
}
#define BULK_COMMIT() asm volatile("cp.async.bulk.commit_group;" ::: "memory")
#define BULK_WAIT0()  asm volatile("cp.async.bulk.wait_group 0;" ::: "memory")
#define FENCE_ASYNC() asm volatile("fence.proxy.async.shared::cta;" ::: "memory")

__device__ __forceinline__ void ldsm4(uint32_t* f, uint32_t a) {
    asm volatile("ldmatrix.sync.aligned.m8n8.x4.shared.b16 {%0,%1,%2,%3}, [%4];\n"
                 : "=r"(f[0]), "=r"(f[1]), "=r"(f[2]), "=r"(f[3]) : "r"(a));
}
__device__ __forceinline__ void mma16816(float* d, const uint32_t* a, uint32_t b0, uint32_t b1) {
    asm volatile(
        "mma.sync.aligned.m16n8k16.row.col.f32.bf16.bf16.f32 "
        "{%0,%1,%2,%3}, {%4,%5,%6,%7}, {%8,%9}, {%0,%1,%2,%3};\n"
        : "+f"(d[0]), "+f"(d[1]), "+f"(d[2]), "+f"(d[3])
        : "r"(a[0]), "r"(a[1]), "r"(a[2]), "r"(a[3]), "r"(b0), "r"(b1));
}

// ---------------------------------------------------------------------------
// Node-side GEMM, BM=64, BN=128 (gridDim.y=2), BK=32; optional second (W,C)
// pair selected by blockIdx.z.
// ---------------------------------------------------------------------------
__global__ __launch_bounds__(256, 2) void gemm_bn128(
    const float* __restrict__ A, int K, const float* __restrict__ W,
    const float* __restrict__ bias, const float* __restrict__ res,
    float* __restrict__ C, int rows, int act,
    const float* __restrict__ W2, float* __restrict__ C2) {
    __shared__ float As[64 * 33];
    __shared__ float Bs[32 * 132];
    if (blockIdx.z == 1) { W = W2; C = C2; }
    int tid = threadIdx.x, tx = tid & 15, ty = tid >> 4;
    int row0 = blockIdx.x * 64;
    int col0 = blockIdx.y * 128;
    float acc[4][8];
#pragma unroll
    for (int i = 0; i < 4; i++)
#pragma unroll
        for (int j = 0; j < 8; j++) acc[i][j] = 0.0f;
    for (int k0 = 0; k0 < K; k0 += 32) {
#pragma unroll
        for (int i = 0; i < 8; i++) {
            int idx = tid + i * 256, r = idx >> 5, c = idx & 31;
            int gr = row0 + r, gk = k0 + c;
            As[r * 33 + c] = (gr < rows && gk < K) ? A[(long)gr * K + gk] : 0.0f;
        }
#pragma unroll
        for (int i = 0; i < 16; i++) {
            int idx = tid + i * 256, r = idx >> 7, c = idx & 127;
            int gk = k0 + r;
            Bs[r * 132 + c] = (gk < K) ? W[(long)gk * 256 + col0 + c] : 0.0f;
        }
        __syncthreads();
#pragma unroll
        for (int kk = 0; kk < 32; kk++) {
            float a[4];
#pragma unroll
            for (int i = 0; i < 4; i++) a[i] = As[(ty * 4 + i) * 33 + kk];
#pragma unroll
            for (int j = 0; j < 8; j++) {
                float b = Bs[kk * 132 + tx + 16 * j];
#pragma unroll
                for (int i = 0; i < 4; i++) acc[i][j] = fmaf(a[i], b, acc[i][j]);
            }
        }
        __syncthreads();
    }
#pragma unroll
    for (int i = 0; i < 4; i++) {
        int r = row0 + ty * 4 + i;
        if (r < rows) {
#pragma unroll
            for (int j = 0; j < 8; j++) {
                int col = col0 + tx + 16 * j;
                float v = acc[i][j];
                if (bias) v += bias[col];
                if (act == 1) v = gelu_f(v);
                if (res) v += res[(long)r * 256 + col];
                C[(long)r * 256 + col] = v;
            }
        }
    }
}

// ---------------------------------------------------------------------------
// Small prep kernels
// ---------------------------------------------------------------------------
__global__ void xcat_kernel(const int* __restrict__ atom_types,
                            const float* __restrict__ x_extra,
                            const float* __restrict__ emb_table,
                            float* __restrict__ xcat, int N) {
    int idx = blockIdx.x * blockDim.x + threadIdx.x;
    if (idx < N * 48) {
        int n = idx / 48, c = idx - n * 48;
        xcat[idx] = (c < 32) ? emb_table[atom_types[n] * 32 + c] : x_extra[n * 16 + (c - 32)];
    }
}

// cz[n] = b_n2m @ (W1a + W1b) + b_r2m @ W1c + b1
__global__ void cz_kernel(const float* __restrict__ b_n2m, const float* __restrict__ b_r2m,
                          const float* __restrict__ b1, const float* __restrict__ w1,
                          float* __restrict__ cz) {
    __shared__ float red[256];
    int n = blockIdx.x, k = threadIdx.x;
    float s = b_n2m[k] * (w1[k * 256 + n] + w1[(256 + k) * 256 + n]);
    s += b_r2m[k] * w1[(512 + k) * 256 + n];
    red[k] = s;
    __syncthreads();
    for (int st = 128; st > 0; st >>= 1) {
        if (k < st) red[k] += red[k + st];
        __syncthreads();
    }
    if (k == 0) cz[n] = red[0] + b1[n];
}

// mlp_w2/3/4 + wr2 -> W^T hi/lo chunk tiles (25 tiles)
__global__ void wprep_kernel(const float* __restrict__ w2, const float* __restrict__ w3,
                             const float* __restrict__ w4, const float* __restrict__ wr2,
                             __nv_bfloat16* __restrict__ wt) {
    int id = blockIdx.x * blockDim.x + threadIdx.x;
    if (id >= 800 * 256) return;
    int kg = id >> 8, n = id & 255;
    const float* w;
    int kl, t;
    if (kg < 256)      { w = w2;  kl = kg;       t = kl >> 5; }
    else if (kg < 512) { w = w3;  kl = kg - 256; t = 8 + (kl >> 5); }
    else if (kg < 768) { w = w4;  kl = kg - 512; t = 16 + (kl >> 5); }
    else               { w = wr2; kl = kg - 768; t = 24; }
    int kk = kl & 31;
    float v = w[(long)kl * 256 + n];
    __nv_bfloat16 h = __float2bfloat16(v);
    __nv_bfloat16 l = __float2bfloat16(v - __bfloat162float(h));
    size_t base = (size_t)t * 16384 + n * 32 + kk;
    wt[base] = h;
    wt[base + 8192] = l;
}

// ---------------------------------------------------------------------------
// Fully fused edge MLP (layers 1..4). CTA = 128 edges x 256 outputs, 16 warps.
// Layer 1: rbf (computed in-kernel, staged hi/lo over the ACT area) @ Wr2 tile
//          + epilogue gathers p[src] + q[dst] + cz -> lrelu -> ACT.
// Layers 2..4: Kc=32 chunks from ACT, 2-deep B ring.
// Final: fp32 rows in SMEM -> cp.reduce.async.bulk scatter.
// Dynamic SMEM:
//   ACT_HI [0,      67584) : 128 rows x 264 bf16 (stride 528B); rbf staging
//                            (128x80B) overlaps its head; FOUT fp32 at the end
//   ACT_LO [67584, 135168)
//   BBUF   [135168,217088): 2 x (hi 256x40 bf16 stride 80B | lo +20480)
// ---------------------------------------------------------------------------
#define ACT_HI 0
#define ACT_LO 67584
#define BBUF   135168
#define DSMEM  217088

__global__ __launch_bounds__(512, 1) void edge_mlp_hmma(
    const float* __restrict__ dists, const float* __restrict__ freq,
    const float* __restrict__ p, const float* __restrict__ q,
    const int* __restrict__ edge_index, const __nv_bfloat16* __restrict__ wt,
    const float* __restrict__ cz, const float* __restrict__ b2,
    const float* __restrict__ b3, const float* __restrict__ b4,
    float* __restrict__ agg, int E) {
    extern __shared__ __align__(16) char dsm[];
    __shared__ int s_src[128], s_dst[128];
    __shared__ float s_bias[1024];   // [0]=cz [256]=b2 [512]=b3 [768]=b4
    __shared__ float s_freq[32];

    const int tid = threadIdx.x;
    const int wid = tid >> 5, lane = tid & 31;
    const int wm = wid >> 2, wn = wid & 3;
    const int r0 = wm * 32;
    const int c0 = wn * 64;
    const int e0 = blockIdx.x * 128;
    const uint32_t sb = smem_u32(dsm);

    for (int i = tid; i < 1024; i += 512) {
        const float* b = (i < 256) ? cz : (i < 512) ? b2 : (i < 768) ? b3 : b4;
        s_bias[i] = b[i & 255];
    }
    if (tid < 32) s_freq[tid] = freq[tid];
    if (tid < 128) {
        int e = e0 + tid;
        s_src[tid] = (e < E) ? edge_index[e] : 0;
        s_dst[tid] = (e < E) ? edge_index[E + e] : 0;
    }

    float acc[2][8][4];
#pragma unroll
    for (int mt = 0; mt < 2; mt++)
#pragma unroll
        for (int nt = 0; nt < 8; nt++)
#pragma unroll
            for (int i = 0; i < 4; i++) acc[mt][nt][i] = 0.0f;

    auto prefetchB = [&](int t, int buf) {
        const char* wsrc = (const char*)wt + (size_t)t * 32768;
        uint32_t dbase = sb + BBUF + buf * 40960;
#pragma unroll
        for (int it = 0; it < 4; it++) {
            int id = tid + it * 512;
            int n = id & 255, rest = id >> 8;
            int seg = rest & 3, hl = rest >> 2;
            cp_async16(dbase + hl * 20480 + n * 80 + seg * 16,
                       wsrc + hl * 16384 + n * 64 + seg * 16);
        }
    };
    auto compute = [&](uint32_t abase, uint32_t astride, uint32_t bbase) {
#pragma unroll
        for (int s = 0; s < 2; s++) {
            int ko2 = s * 32;
            uint32_t ah[2][4], al[2][4];
#pragma unroll
            for (int mt = 0; mt < 2; mt++) {
                uint32_t ad = abase + (uint32_t)(r0 + mt * 16 + (lane & 15)) * astride +
                              ko2 + ((lane >> 4) << 4);
                ldsm4(ah[mt], ad);
                ldsm4(al[mt], ad + (uint32_t)(ACT_LO - ACT_HI));
            }
#pragma unroll
            for (int qd = 0; qd < 4; qd++) {
                int n = c0 + qd * 16 + (lane & 7) + ((lane & 16) >> 1);
                uint32_t bd = bbase + (uint32_t)n * 80 + ko2 + ((lane & 8) << 1);
                uint32_t bh[4], bl[4];
                ldsm4(bh, bd);
                ldsm4(bl, bd + 20480);
#pragma unroll
                for (int mt = 0; mt < 2; mt++) {
                    mma16816(acc[mt][2 * qd + 0], ah[mt], bh[0], bh[1]);
                    mma16816(acc[mt][2 * qd + 1], ah[mt], bh[2], bh[3]);
                    mma16816(acc[mt][2 * qd + 0], al[mt], bh[0], bh[1]);
                    mma16816(acc[mt][2 * qd + 1], al[mt], bh[2], bh[3]);
                    mma16816(acc[mt][2 * qd + 0], ah[mt], bl[0], bl[1]);
                    mma16816(acc[mt][2 * qd + 1], ah[mt], bl[2], bl[3]);
                }
            }
        }
    };
    auto epilogue_act = [&](int bidx) {
#pragma unroll
        for (int mt = 0; mt < 2; mt++) {
#pragma unroll
            for (int nt = 0; nt < 8; nt++) {
                int ra = r0 + mt * 16 + (lane >> 2);
                int ca = c0 + nt * 8 + 2 * (lane & 3);
                float bv0 = s_bias[bidx * 256 + ca], bv1 = s_bias[bidx * 256 + ca + 1];
#pragma unroll
                for (int half = 0; half < 2; half++) {
                    int r = ra + half * 8;
                    float v0 = lrelu_f(acc[mt][nt][half * 2 + 0] + bv0);
                    float v1 = lrelu_f(acc[mt][nt][half * 2 + 1] + bv1);
                    __nv_bfloat16 h0 = __float2bfloat16(v0);
                    __nv_bfloat16 h1 = __float2bfloat16(v1);
                    __nv_bfloat162 hp; hp.x = h0; hp.y = h1;
                    __nv_bfloat162 lp;
                    lp.x = __float2bfloat16(v0 - __bfloat162float(h0));
                    lp.y = __float2bfloat16(v1 - __bfloat162float(h1));
                    uint32_t off = (uint32_t)r * 528 + (uint32_t)ca * 2;
                    *(__nv_bfloat162*)(dsm + ACT_HI + off) = hp;
                    *(__nv_bfloat162*)(dsm + ACT_LO + off) = lp;
                    acc[mt][nt][half * 2 + 0] = 0.0f;
                    acc[mt][nt][half * 2 + 1] = 0.0f;
                }
            }
        }
    };

    // prime B ring: chunk0 = Wr2 tile (24) -> buf0, chunk1 = W2 tile 0 -> buf1
    prefetchB(24, 0);
    CP_COMMIT();
    prefetchB(0, 1);
    CP_COMMIT();

    __syncthreads();  // s_freq/s_src/s_dst/s_bias visible

    // rbf staging: thread -> row r = tid>>2, k block (tid&3)*8..+8
    {
        int r = tid >> 2, k0 = (tid & 3) * 8;
        int e = e0 + r;
        float d = ((e < E) ? dists[e] : 5.0f) * 0.2f;
        float d2 = d * d, d5 = d2 * d2 * d;
        float env = 1.0f / d + d5 * (-28.0f + d * (48.0f + d * (-21.0f)));
#pragma unroll
        for (int j = 0; j < 8; j++) {
            float v = env * sinf(s_freq[k0 + j] * d);
            __nv_bfloat16 h = __float2bfloat16(v);
            __nv_bfloat16 l = __float2bfloat16(v - __bfloat162float(h));
            uint32_t off = (uint32_t)r * 80 + (uint32_t)(k0 + j) * 2;
            *(__nv_bfloat16*)(dsm + ACT_HI + off) = h;
            *(__nv_bfloat16*)(dsm + ACT_LO + off) = l;
        }
    }

    // 25 chunks: g=0 -> layer1 (rbf, tile 24); g=1..8 W2; 9..16 W3; 17..24 W4
    for (int g = 0; g < 25; g++) {
        if (g < 24) { CP_WAIT1(); } else { CP_WAIT0(); }
        __syncthreads();                  // B(g) + (rbf STS at g=0 / new ACT) visible
        if (g == 0)
            compute(sb + ACT_HI, 80u, sb + BBUF);
        else
            compute(sb + ACT_HI + (uint32_t)((g - 1) & 7) * 64, 528u,
                    sb + BBUF + (g & 1) * 40960);
        __syncthreads();                  // all done reading buf g&1 / ACT region
        if (g + 2 < 25) {
            prefetchB(g + 1, g & 1);      // tile for chunk g+2 is (g+2)-1 = g+1
            CP_COMMIT();
        }
        if (g == 0) {
            // layer-1 epilogue: acc + p[src] + q[dst] + cz -> lrelu -> ACT
#pragma unroll
            for (int mt = 0; mt < 2; mt++) {
#pragma unroll
                for (int nt = 0; nt < 8; nt++) {
                    int ra = r0 + mt * 16 + (lane >> 2);
                    int ca = c0 + nt * 8 + 2 * (lane & 3);
                    float bv0 = s_bias[ca], bv1 = s_bias[ca + 1];
#pragma unroll
                    for (int half = 0; half < 2; half++) {
                        int r = ra + half * 8;
                        float2 pv = *(const float2*)(p + (size_t)s_src[r] * 256 + ca);
                        float2 qv = *(const float2*)(q + (size_t)s_dst[r] * 256 + ca);
                        float v0 = lrelu_f(acc[mt][nt][half * 2 + 0] + pv.x + qv.x + bv0);
                        float v1 = lrelu_f(acc[mt][nt][half * 2 + 1] + pv.y + qv.y + bv1);
                        __nv_bfloat16 h0 = __float2bfloat16(v0);
                        __nv_bfloat16 h1 = __float2bfloat16(v1);
                        __nv_bfloat162 hp; hp.x = h0; hp.y = h1;
                        __nv_bfloat162 lp;
                        lp.x = __float2bfloat16(v0 - __bfloat162float(h0));
                        lp.y = __float2bfloat16(v1 - __bfloat162float(h1));
                        uint32_t off = (uint32_t)r * 528 + (uint32_t)ca * 2;
                        *(__nv_bfloat162*)(dsm + ACT_HI + off) = hp;
                        *(__nv_bfloat162*)(dsm + ACT_LO + off) = lp;
                        acc[mt][nt][half * 2 + 0] = 0.0f;
                        acc[mt][nt][half * 2 + 1] = 0.0f;
                    }
                }
            }
        } else if (g == 8) {
            epilogue_act(1);
        } else if (g == 16) {
            epilogue_act(2);
        } else if (g == 24) {
            // final: bias -> fp32 rows in SMEM (reuse ACT area), bulk-reduce
#pragma unroll
            for (int mt = 0; mt < 2; mt++) {
#pragma unroll
                for (int nt = 0; nt < 8; nt++) {
                    int ra = r0 + mt * 16 + (lane >> 2);
                    int ca = c0 + nt * 8 + 2 * (lane & 3);
                    float bv0 = s_bias[768 + ca], bv1 = s_bias[768 + ca + 1];
#pragma unroll
                    for (int half = 0; half < 2; half++) {
                        int r = ra + half * 8;
                        float2 v;
                        v.x = acc[mt][nt][half * 2 + 0] + bv0;
                        v.y = acc[mt][nt][half * 2 + 1] + bv1;
                        *(float2*)(dsm + (uint32_t)r * 1024 + (uint32_t)ca * 4) = v;
                    }
                }
            }
            FENCE_ASYNC();
            __syncthreads();
            if (tid < 128 && (e0 + tid) < E) {
                bulk_reduce_add_f32(agg + (size_t)s_dst[tid] * 256,
                                    sb + (uint32_t)tid * 1024, 1024);
            }
            BULK_COMMIT();
            BULK_WAIT0();
        }
    }
}

// ---------------------------------------------------------------------------
extern "C" void kernel_launch(void* const* d_in, const int* in_sizes, int n_in,
                              void* d_out, int out_size) {
    const int* atom_types = (const int*)d_in[0];
    const float* x_extra = (const float*)d_in[1];
    const int* edge_index = (const int*)d_in[2];
    const float* dists = (const float*)d_in[3];
    const float* freq = (const float*)d_in[4];
    const float* emb_table = (const float*)d_in[5];
    const float* w_emb = (const float*)d_in[6];
    const float* b_emb = (const float*)d_in[7];
    const float* w_n2m = (const float*)d_in[8];
    const float* b_n2m = (const float*)d_in[9];
    const float* w_r2m = (const float*)d_in[10];
    const float* b_r2m = (const float*)d_in[11];
    const float* w_m2n = (const float*)d_in[12];
    const float* mw1 = (const float*)d_in[13];
    const float* mb1 = (const float*)d_in[14];
    const float* mw2 = (const float*)d_in[15];
    const float* mb2 = (const float*)d_in[16];
    const float* mw3 = (const float*)d_in[17];
    const float* mb3 = (const float*)d_in[18];
    const float* mw4 = (const float*)d_in[19];
    const float* mb4 = (const float*)d_in[20];
    const float* fw1 = (const float*)d_in[21];
    const float* fb1 = (const float*)d_in[22];
    const float* fw2 = (const float*)d_in[23];
    const float* fb2 = (const float*)d_in[24];
    float* out = (float*)d_out;

    int N = in_sizes[0];
    int E = in_sizes[2] / 2;

    float *p_xcat, *p_h, *p_p, *p_q, *p_agg, *p_t, *p_u;
    float *p_wpa, *p_wqb, *p_wr2, *p_cz;
    __nv_bfloat16 *p_wt;
    cudaGetSymbolAddress((void**)&p_xcat, g_xcat);
    cudaGetSymbolAddress((void**)&p_h, g_h);
    cudaGetSymbolAddress((void**)&p_p, g_p);
    cudaGetSymbolAddress((void**)&p_q, g_q);
    cudaGetSymbolAddress((void**)&p_agg, g_agg);
    cudaGetSymbolAddress((void**)&p_t, g_t);
    cudaGetSymbolAddress((void**)&p_u, g_u);
    cudaGetSymbolAddress((void**)&p_wpa, g_wpa);
    cudaGetSymbolAddress((void**)&p_wqb, g_wqb);
    cudaGetSymbolAddress((void**)&p_wr2, g_wr2);
    cudaGetSymbolAddress((void**)&p_cz, g_cz);
    cudaGetSymbolAddress((void**)&p_wt, g_wt);

    cudaFuncSetAttribute(edge_mlp_hmma, cudaFuncAttributeMaxDynamicSharedMemorySize, DSMEM);

    dim3 gN((N + 63) / 64, 2);
    dim3 gPQ((N + 63) / 64, 2, 2);
    dim3 gFold(4, 2, 2), g32(1, 2);
    int gE128 = (E + 127) / 128;

    // weight folding preps
    gemm_bn128<<<gFold, 256>>>(w_n2m, 256, mw1, nullptr, nullptr, p_wpa, 256, 0,
                               mw1 + 256 * 256, p_wqb);
    gemm_bn128<<<g32, 256>>>(w_r2m, 256, mw1 + 512 * 256, nullptr, nullptr, p_wr2, 32, 0,
                             nullptr, nullptr);
    cz_kernel<<<256, 256>>>(b_n2m, b_r2m, mb1, mw1, p_cz);
    wprep_kernel<<<800, 256>>>(mw2, mw3, mw4, p_wr2, p_wt);

    // node pipeline
    xcat_kernel<<<(N * 48 + 255) / 256, 256>>>(atom_types, x_extra, emb_table, p_xcat, N);
    gemm_bn128<<<gN, 256>>>(p_xcat, 48, w_emb, b_emb, nullptr, p_h, N, 1, nullptr, nullptr);
    gemm_bn128<<<gPQ, 256>>>(p_h, 256, p_wpa, nullptr, nullptr, p_p, N, 0, p_wqb, p_q);

    // fused edge pipeline
    cudaMemsetAsync(p_agg, 0, (size_t)N * 256 * sizeof(float));
    edge_mlp_hmma<<<gE128, 512, DSMEM>>>(dists, freq, p_p, p_q, edge_index, p_wt,
                                         p_cz, mb2, mb3, mb4, p_agg, E);

    // output
    gemm_bn128<<<gN, 256>>>(p_agg, 256, w_m2n, nullptr, p_h, p_t, N, 0, nullptr, nullptr);
    gemm_bn128<<<gN, 256>>>(p_t, 256, fw1, fb1, nullptr, p_u, N, 1, nullptr, nullptr);
    gemm_bn128<<<gN, 256>>>(p_u, 256, fw2, fb2, p_t, out, N, 0, nullptr, nullptr);
}